// round 7
// baseline (speedup 1.0000x reference)
#include <cuda_runtime.h>
#include <math.h>
#include <stdint.h>

#define B 8
#define OUTD 592002
#define WPSTR 328320   // per-sample float2 count in g_wp

// ---------------- scratch (device globals; no allocation allowed) ----------------
__device__ float g_bufA[(size_t)B * 128 * 256 * 256];
__device__ float g_bufB[(size_t)B * 128 * 256 * 256];
__device__ float g_skip1[(size_t)B * 64 * 256 * 256];
__device__ float g_skip2[(size_t)B * 64 * 128 * 128];
__device__ float g_skip3[(size_t)B * 64 * 64 * 64];
__device__ float g_w[(size_t)B * OUTD];                    // flat generated weights
__device__ __align__(16) float2 g_wp[(size_t)B * WPSTR];   // paired conv weights
__device__ float g_h2[B * 32];

// ---------------- constant tables ----------------
__constant__ int cKOFF[14] = {0, 1152, 38016, 74880, 111744, 148608, 185472, 222336,
                              259200, 332928, 369792, 443520, 480384, 554112};
__constant__ int cCIN[14]  = {2, 64, 64, 64, 64, 64, 64, 64, 128, 64, 128, 64, 128, 64};
__constant__ int cWPOFF[14]= {0, 640, 21120, 41600, 62080, 82560, 103040, 123520,
                              144000, 184960, 205440, 246400, 266880, 307840};
__constant__ int cCUME[14] = {0, 576, 19008, 37440, 55872, 74304, 92736, 111168,
                              129600, 166464, 184896, 221760, 240192, 277056};

// ---------------- packed fp32 + cp.async helpers ----------------
__device__ __forceinline__ void fma2(unsigned long long& acc, unsigned long long x,
                                     unsigned long long w)
{
    asm("fma.rn.f32x2 %0, %1, %2, %0;" : "+l"(acc) : "l"(x), "l"(w));
}
__device__ __forceinline__ unsigned long long pack2b(float a)
{
    unsigned long long r;
    asm("mov.b64 %0, {%1, %1};" : "=l"(r) : "f"(a));
    return r;
}
__device__ __forceinline__ float2 unpack2(unsigned long long v)
{
    float2 r;
    asm("mov.b64 {%0, %1}, %2;" : "=f"(r.x), "=f"(r.y) : "l"(v));
    return r;
}
__device__ __forceinline__ void cp4(uint32_t dst, const void* src)
{
    asm volatile("cp.async.ca.shared.global [%0], [%1], 4;" :: "r"(dst), "l"(src) : "memory");
}
__device__ __forceinline__ void cp16(uint32_t dst, const void* src)
{
    asm volatile("cp.async.cg.shared.global [%0], [%1], 16;" :: "r"(dst), "l"(src) : "memory");
}
__device__ __forceinline__ void cp16z(uint32_t dst, const void* src, int sz)
{
    // src_size variant: if sz==0, 16 bytes of zeros are written, nothing is read
    asm volatile("cp.async.cg.shared.global [%0], [%1], 16, %2;"
                 :: "r"(dst), "l"(src), "r"(sz) : "memory");
}
__device__ __forceinline__ void cp_commit()
{
    asm volatile("cp.async.commit_group;" ::: "memory");
}
__device__ __forceinline__ void cp_wait1()
{
    asm volatile("cp.async.wait_group 1;" ::: "memory");
}
__device__ __forceinline__ void cp_wait0()
{
    asm volatile("cp.async.wait_group 0;" ::: "memory");
}

// ---------------- hypernet stage 1 (+ zero l1) ----------------
__global__ void hyper1_kernel(const float* __restrict__ hp, const float* __restrict__ W1,
                              const float* __restrict__ b1, const float* __restrict__ W2,
                              const float* __restrict__ b2, float* __restrict__ l1)
{
    __shared__ float h1[B][32];
    int b = threadIdx.x >> 5;
    int i = threadIdx.x & 31;
    if (threadIdx.x < B) l1[threadIdx.x] = 0.f;
    h1[b][i] = hp[b] * W1[i] + b1[i];   // IN_DIM = 1
    __syncthreads();
    float a = b2[i];
#pragma unroll
    for (int k = 0; k < 32; k++) a += h1[b][k] * W2[i * 32 + k];
    g_h2[b * 32 + i] = a;
}

// ---------------- hypernet stage 2 ----------------
__global__ void weightgen_kernel(const float* __restrict__ Wo, const float* __restrict__ bo,
                                 float* __restrict__ l1out)
{
    __shared__ float sh2[B * 32];
    __shared__ float wsum[8][B];
    int tid = threadIdx.x;
    sh2[tid] = g_h2[tid];
    __syncthreads();

    int j = blockIdx.x * 256 + tid;
    float s[B];
#pragma unroll
    for (int b = 0; b < B; b++) s[b] = 0.f;

    if (j < OUTD) {
        float wr[32];
        const float* row = Wo + (size_t)j * 32;
#pragma unroll
        for (int i = 0; i < 32; i++) wr[i] = row[i];
        float bj = bo[j];
#pragma unroll
        for (int b = 0; b < B; b++) {
            float a = bj;
#pragma unroll
            for (int i = 0; i < 32; i++) a += wr[i] * sh2[b * 32 + i];
            float w = tanhf(a);
            g_w[(size_t)b * OUTD + j] = w;
            s[b] = fabsf(w);
        }
    }
    int warp = tid >> 5, lane = tid & 31;
#pragma unroll
    for (int b = 0; b < B; b++) {
        float v = s[b];
        for (int off = 16; off > 0; off >>= 1) v += __shfl_xor_sync(0xFFFFFFFFu, v, off);
        if (lane == 0) wsum[warp][b] = v;
    }
    __syncthreads();
    if (tid < B) {
        float a = 0.f;
#pragma unroll
        for (int w = 0; w < 8; w++) a += wsum[w][tid];
        atomicAdd(&l1out[tid], a);
    }
}

// ---------------- repack conv weights into paired layout ----------------
// per (sample, layer): [(c*32 + ocp)*10 + k] float2 = (w[2ocp][c][k], w[2ocp+1][c][k])
__global__ void repack_kernel()
{
    const int PER = 295488;
    int e = blockIdx.x * 256 + threadIdx.x;
    if (e >= B * PER) return;
    int b = e / PER;
    int r = e - b * PER;
    int l = 13;
#pragma unroll
    for (int i = 13; i > 0; i--)
        if (r < cCUME[i]) l = i - 1;
    int q = r - cCUME[l];
    int cin = cCIN[l];
    int c   = q / 288;
    int t   = q - c * 288;
    int ocp = t / 9;
    int k   = t - ocp * 9;
    const float* wb = g_w + (size_t)b * OUTD + cKOFF[l];
    float w0 = wb[((2 * ocp) * cin + c) * 9 + k];
    float w1 = wb[((2 * ocp + 1) * cin + c) * 9 + k];
    float2* dst = &g_wp[(size_t)b * WPSTR + cWPOFF[l] + (c * 32 + ocp) * 10 + k];
    *dst = make_float2(w0, w1);
    if (k == 0) dst[9] = make_float2(0.f, 0.f);   // pad slot
}

// ---------------- 3x3 conv: cp16 staging, LDS.128 weights, f32x2 math ----------------
// Block: 256 threads, 32x32 tile, OCB oc. Thread: 2x2 px x OCB oc (oc-paired f32x2).
// smem input rows are 40 wide: col c <-> gx = tx0-4+c.
template<int CIN, int OCB, bool NHWC>
__global__ __launch_bounds__(256, 2) void conv3x3_kernel(
    const float* __restrict__ in, float* __restrict__ out,
    const float2* __restrict__ wp, const float* __restrict__ wbuf,
    int wpoff, int boff, int H, int relu)
{
    constexpr int CS   = (CIN < 4) ? CIN : 4;
    constexpr int OCP  = OCB / 2;
    constexpr int G    = CIN / CS;
    constexpr int CROW = 34 * 40;          // floats per channel tile
    constexpr int INSZ = CS * CROW;        // floats per buffer
    constexpr int WPC  = OCP * 10;         // float2 per channel (weights)
    constexpr int WCHK = CS * OCP * 5;     // 16B chunks per buffer

    __shared__ __align__(16) float  sIn[2 * INSZ];
    __shared__ __align__(16) float2 sW[2 * CS * WPC];

    int b   = blockIdx.z;
    int op0 = blockIdx.y * OCP;
    int tiles = H >> 5;
    int ty0 = (blockIdx.x / tiles) << 5;
    int tx0 = (blockIdx.x % tiles) << 5;
    int tid = threadIdx.x;
    int tx = tid & 15, ty = tid >> 4;

    const float* inb = NHWC ? (in + (size_t)b * H * H * CIN)
                            : (in + (size_t)b * CIN * H * H);
    const char* wpb = (const char*)(wp + (size_t)b * WPSTR + wpoff);
    uint32_t siAddr = (uint32_t)__cvta_generic_to_shared(sIn);
    uint32_t swAddr = (uint32_t)__cvta_generic_to_shared(sW);

    auto stage = [&](int g, int buf) {
        int c0 = g * CS;
        if (NHWC) {
            // per-element cp4 (layer 0 only, CIN=2)
            for (int idx = tid; idx < CS * 1156; idx += 256) {
                int cs = idx / 1156, rem = idx - cs * 1156;
                int r = rem / 34, cc = rem - r * 34;
                int gy = ty0 - 1 + r, gx = tx0 - 1 + cc;
                int soff = buf * INSZ + cs * CROW + r * 40 + cc + 3;
                if ((unsigned)gy < (unsigned)H && (unsigned)gx < (unsigned)H)
                    cp4(siAddr + soff * 4, &inb[((size_t)gy * H + gx) * CIN + c0 + cs]);
                else
                    sIn[soff] = 0.f;
            }
        } else {
            // 16B chunks, zero-fill OOB via src_size=0
            for (int idx = tid; idx < CS * 340; idx += 256) {
                int cs = idx / 340, rem = idx - cs * 340;
                int r = rem / 10, j = rem - r * 10;
                int gy = ty0 - 1 + r;
                int gxb = tx0 - 4 + 4 * j;
                bool ok = ((unsigned)gy < (unsigned)H) && ((unsigned)gxb < (unsigned)H);
                const float* src = ok ? &inb[(size_t)(c0 + cs) * H * H + (size_t)gy * H + gxb]
                                      : inb;
                cp16z(siAddr + (buf * INSZ + cs * CROW + r * 40 + 4 * j) * 4, src, ok ? 16 : 0);
            }
        }
        // weights: contiguous 16B chunks
        for (int idx = tid; idx < WCHK; idx += 256) {
            int cs = idx / (OCP * 5), rem = idx - cs * (OCP * 5);
            const char* src = wpb + ((size_t)(c0 + cs) * 32 + op0) * 80 + rem * 16;
            uint32_t dst = swAddr + (buf * CS * WPC + cs * WPC) * 8 + rem * 16;
            cp16(dst, src);
        }
    };

    unsigned long long acc[OCP][4];
#pragma unroll
    for (int i = 0; i < OCP; i++)
#pragma unroll
        for (int p = 0; p < 4; p++) acc[i][p] = 0ull;

    stage(0, 0);
    cp_commit();

    for (int g = 0; g < G; g++) {
        if (g + 1 < G) { stage(g + 1, (g + 1) & 1); cp_commit(); cp_wait1(); }
        else           { cp_wait0(); }
        __syncthreads();

        const float*  sib = sIn + (g & 1) * INSZ;
        const float2* swb = sW + (g & 1) * CS * WPC;

#pragma unroll
        for (int cs = 0; cs < CS; cs++) {
            const float* si = sib + cs * CROW + (2 * ty) * 40 + 2 * tx + 3;
            unsigned long long xp[16];
#pragma unroll
            for (int r = 0; r < 4; r++) {
                float a0 = si[r * 40];
                float2 am = *(const float2*)(si + r * 40 + 1);
                float a3 = si[r * 40 + 3];
                xp[r * 4 + 0] = pack2b(a0);
                xp[r * 4 + 1] = pack2b(am.x);
                xp[r * 4 + 2] = pack2b(am.y);
                xp[r * 4 + 3] = pack2b(a3);
            }
            const ulonglong2* wq = (const ulonglong2*)(swb + cs * WPC);
            const unsigned long long* wq1 = (const unsigned long long*)wq;

#define TAP(o, ky, kx, w) \
            fma2(acc[o][0], xp[(0 + ky) * 4 + 0 + kx], (w)); \
            fma2(acc[o][1], xp[(0 + ky) * 4 + 1 + kx], (w)); \
            fma2(acc[o][2], xp[(1 + ky) * 4 + 0 + kx], (w)); \
            fma2(acc[o][3], xp[(1 + ky) * 4 + 1 + kx], (w));

#pragma unroll
            for (int ocp = 0; ocp < OCP; ocp++) {
                ulonglong2 wA = wq[ocp * 5 + 0];
                TAP(ocp, 0, 0, wA.x); TAP(ocp, 0, 1, wA.y);
                ulonglong2 wB = wq[ocp * 5 + 1];
                TAP(ocp, 0, 2, wB.x); TAP(ocp, 1, 0, wB.y);
                ulonglong2 wC = wq[ocp * 5 + 2];
                TAP(ocp, 1, 1, wC.x); TAP(ocp, 1, 2, wC.y);
                ulonglong2 wD = wq[ocp * 5 + 3];
                TAP(ocp, 2, 0, wD.x); TAP(ocp, 2, 1, wD.y);
                unsigned long long wE = wq1[ocp * 10 + 8];
                TAP(ocp, 2, 2, wE);
            }
#undef TAP
        }
        __syncthreads();
    }

    // epilogue: bias + relu + store (NCHW)
    const float* wb = wbuf + (size_t)b * OUTD;
#pragma unroll
    for (int ocp = 0; ocp < OCP; ocp++) {
        int oc = 2 * (op0 + ocp);
        float b0 = wb[boff + oc];
        float b1 = wb[boff + oc + 1];
        float* o0 = out + (((size_t)b * 64 + oc) * H) * H;
        float* o1 = o0 + (size_t)H * H;
#pragma unroll
        for (int py = 0; py < 2; py++)
#pragma unroll
            for (int px = 0; px < 2; px++) {
                float2 v = unpack2(acc[ocp][py * 2 + px]);
                v.x += b0; v.y += b1;
                if (relu) { v.x = fmaxf(v.x, 0.f); v.y = fmaxf(v.y, 0.f); }
                int y = ty0 + 2 * ty + py, x = tx0 + 2 * tx + px;
                o0[y * H + x] = v.x;
                o1[y * H + x] = v.y;
            }
    }
}

// ---------------- 2x2 maxpool ----------------
__global__ void maxpool_kernel(const float* __restrict__ in, float* __restrict__ out, int H, int W)
{
    int Ho = H >> 1, Wo = W >> 1;
    int total = B * 64 * Ho * Wo;
    int idx = blockIdx.x * blockDim.x + threadIdx.x;
    if (idx >= total) return;
    int xo = idx % Wo;
    int yo = (idx / Wo) % Ho;
    int bc = idx / (Wo * Ho);
    const float* p = in + (size_t)bc * H * W + (yo * 2) * W + xo * 2;
    float v = fmaxf(fmaxf(p[0], p[1]), fmaxf(p[W], p[W + 1]));
    out[idx] = v;
}

// ---------------- fused bilinear upsample x2 + skip copy ----------------
__global__ void up_concat_kernel(const float* __restrict__ in, const float* __restrict__ skip,
                                 float* __restrict__ out, int H, int W)
{
    int Ho = H * 2, Wo = W * 2;
    int total = B * 64 * Ho * Wo;
    int idx = blockIdx.x * blockDim.x + threadIdx.x;
    if (idx >= total) return;
    int xo = idx % Wo;
    int yo = (idx / Wo) % Ho;
    int c  = (idx / (Wo * Ho)) % 64;
    int b  = idx / (Wo * Ho * 64);

    float ys = (float)yo * (float)(H - 1) / (float)(Ho - 1);
    float xs = (float)xo * (float)(W - 1) / (float)(Wo - 1);
    int y0 = (int)floorf(ys); int y1 = min(y0 + 1, H - 1);
    int x0 = (int)floorf(xs); int x1 = min(x0 + 1, W - 1);
    float wy = ys - (float)y0, wx = xs - (float)x0;

    const float* p = in + ((size_t)b * 64 + c) * H * W;
    float r0 = p[y0 * W + x0] * (1.f - wy) + p[y1 * W + x0] * wy;
    float r1 = p[y0 * W + x1] * (1.f - wy) + p[y1 * W + x1] * wy;
    float v = r0 * (1.f - wx) + r1 * wx;

    size_t obase = (((size_t)b * 128 + c) * Ho + yo) * Wo + xo;
    out[obase] = v;
    out[obase + (size_t)64 * Ho * Wo] =
        skip[(((size_t)b * 64 + c) * Ho + yo) * Wo + xo];
}

// ---------------- final 1x1 conv (64->2) + residual + NCHW->NHWC ----------------
__global__ void final_kernel(const float* __restrict__ in, const float* __restrict__ zf,
                             const float* __restrict__ wbuf, int woff, int boff,
                             float* __restrict__ out)
{
    __shared__ float sw[130];
    int b  = blockIdx.y;
    int tid = threadIdx.x;
    const float* wb = wbuf + (size_t)b * OUTD;
    if (tid < 128) sw[tid] = wb[woff + tid];
    else if (tid < 130) sw[tid] = wb[boff + (tid - 128)];
    __syncthreads();
    int hw = blockIdx.x * 256 + tid;
    const float* inb = in + (size_t)b * 64 * 65536 + hw;
    float a0 = sw[128], a1 = sw[129];
#pragma unroll 8
    for (int c = 0; c < 64; c++) {
        float v = inb[(size_t)c * 65536];
        a0 = fmaf(v, sw[c], a0);
        a1 = fmaf(v, sw[64 + c], a1);
    }
    size_t o = ((size_t)b * 65536 + hw) * 2;
    out[o]     = zf[o]     + a0;
    out[o + 1] = zf[o + 1] + a1;
}

// ---------------- host side ----------------
static const int KOFF[15] = {0, 1152, 38016, 74880, 111744, 148608, 185472, 222336,
                             259200, 332928, 369792, 443520, 480384, 554112, 590976};
static const int CINL[15] = {2, 64, 64, 64, 64, 64, 64, 64, 128, 64, 128, 64, 128, 64, 64};
static const int WPOFF[14]= {0, 640, 21120, 41600, 62080, 82560, 103040, 123520,
                             144000, 184960, 205440, 246400, 266880, 307840};
#define BOFF(i) (591104 + 64 * (i))

static inline void launch_conv(const float* in, float* out, const float2* wp,
                               const float* wb, int layer, int H, int relu)
{
    int cin = CINL[layer];
    int tiles = (H / 32) * (H / 32);
    if (H <= 64) {
        dim3 gs(tiles, 8, B);   // OCB=8
        if (cin == 64)
            conv3x3_kernel<64, 8, false><<<gs, 256>>>(in, out, wp, wb, WPOFF[layer], BOFF(layer), H, relu);
        else
            conv3x3_kernel<128, 8, false><<<gs, 256>>>(in, out, wp, wb, WPOFF[layer], BOFF(layer), H, relu);
    } else {
        dim3 gs(tiles, 4, B);   // OCB=16
        if (cin == 2)
            conv3x3_kernel<2, 16, true><<<gs, 256>>>(in, out, wp, wb, WPOFF[layer], BOFF(layer), H, relu);
        else if (cin == 64)
            conv3x3_kernel<64, 16, false><<<gs, 256>>>(in, out, wp, wb, WPOFF[layer], BOFF(layer), H, relu);
        else
            conv3x3_kernel<128, 16, false><<<gs, 256>>>(in, out, wp, wb, WPOFF[layer], BOFF(layer), H, relu);
    }
}

extern "C" void kernel_launch(void* const* d_in, const int* in_sizes, int n_in,
                              void* d_out, int out_size)
{
    const float* zf = (const float*)d_in[0];
    const float* hp = (const float*)d_in[2];
    const float* W1 = (const float*)d_in[3];
    const float* b1 = (const float*)d_in[4];
    const float* W2 = (const float*)d_in[5];
    const float* b2 = (const float*)d_in[6];
    const float* Wo = (const float*)d_in[7];
    const float* bo = (const float*)d_in[8];
    float* out = (float*)d_out;
    float* l1 = out + (size_t)B * 256 * 256 * 2;

    float *pA, *pB, *pS1, *pS2, *pS3, *pW;
    float2* pWP;
    cudaGetSymbolAddress((void**)&pA,  g_bufA);
    cudaGetSymbolAddress((void**)&pB,  g_bufB);
    cudaGetSymbolAddress((void**)&pS1, g_skip1);
    cudaGetSymbolAddress((void**)&pS2, g_skip2);
    cudaGetSymbolAddress((void**)&pS3, g_skip3);
    cudaGetSymbolAddress((void**)&pW,  g_w);
    cudaGetSymbolAddress((void**)&pWP, g_wp);

    hyper1_kernel<<<1, 256>>>(hp, W1, b1, W2, b2, l1);
    weightgen_kernel<<<(OUTD + 255) / 256, 256>>>(Wo, bo, l1);
    repack_kernel<<<(B * 295488 + 255) / 256, 256>>>();

    // encoder (layer 0 reads zf NHWC directly)
    launch_conv(zf, pA, pWP, pW, 0, 256, 1);
    launch_conv(pA, pS1, pWP, pW, 1, 256, 1);
    { int n = B * 64 * 128 * 128; maxpool_kernel<<<(n + 255) / 256, 256>>>(pS1, pA, 256, 256); }
    launch_conv(pA, pB, pWP, pW, 2, 128, 1);
    launch_conv(pB, pS2, pWP, pW, 3, 128, 1);
    { int n = B * 64 * 64 * 64;   maxpool_kernel<<<(n + 255) / 256, 256>>>(pS2, pA, 128, 128); }
    launch_conv(pA, pB, pWP, pW, 4, 64, 1);
    launch_conv(pB, pS3, pWP, pW, 5, 64, 1);
    { int n = B * 64 * 32 * 32;   maxpool_kernel<<<(n + 255) / 256, 256>>>(pS3, pA, 64, 64); }
    launch_conv(pA, pB, pWP, pW, 6, 32, 1);
    launch_conv(pB, pA, pWP, pW, 7, 32, 1);

    // decoder level 1 (32 -> 64)
    { int n = B * 64 * 64 * 64;   up_concat_kernel<<<(n + 255) / 256, 256>>>(pA, pS3, pB, 32, 32); }
    launch_conv(pB, pA, pWP, pW, 8, 64, 1);
    launch_conv(pA, pB, pWP, pW, 9, 64, 1);

    // decoder level 2 (64 -> 128)
    { int n = B * 64 * 128 * 128; up_concat_kernel<<<(n + 255) / 256, 256>>>(pB, pS2, pA, 64, 64); }
    launch_conv(pA, pB, pWP, pW, 10, 128, 1);
    launch_conv(pB, pA, pWP, pW, 11, 128, 1);

    // decoder level 3 (128 -> 256)
    { int n = B * 64 * 256 * 256; up_concat_kernel<<<(n + 255) / 256, 256>>>(pA, pS1, pB, 128, 128); }
    launch_conv(pB, pA, pWP, pW, 12, 256, 1);
    launch_conv(pA, pB, pWP, pW, 13, 256, 1);

    {
        dim3 gs(65536 / 256, B);
        final_kernel<<<gs, 256>>>(pB, zf, pW, KOFF[14], BOFF(14), out);
    }
}

// round 9
// speedup vs baseline: 1.5834x; 1.5834x over previous
#include <cuda_runtime.h>
#include <cuda_bf16.h>
#include <math.h>
#include <stdint.h>

#define B 8
#define OUTD 592002
#define WMTOT 589824
typedef __nv_bfloat16 bf;

// ---------------- device globals ----------------
__device__ float g_w[(size_t)B * OUTD];
__device__ float g_h2[B * 32];
__device__ __align__(16) float2 g_wp0[(size_t)B * 640];
__device__ __align__(16) bf g_wmh[(size_t)B * WMTOT];
__device__ __align__(16) bf g_wml[(size_t)B * WMTOT];
__device__ __align__(16) bf g_Ah[(size_t)B * 128 * 65536];
__device__ __align__(16) bf g_Al[(size_t)B * 128 * 65536];
__device__ __align__(16) bf g_Bh[(size_t)B * 128 * 65536];
__device__ __align__(16) bf g_Bl[(size_t)B * 128 * 65536];
__device__ __align__(16) bf g_S1h[(size_t)B * 64 * 65536];
__device__ __align__(16) bf g_S1l[(size_t)B * 64 * 65536];
__device__ __align__(16) bf g_S2h[(size_t)B * 64 * 16384];
__device__ __align__(16) bf g_S2l[(size_t)B * 64 * 16384];
__device__ __align__(16) bf g_S3h[(size_t)B * 64 * 4096];
__device__ __align__(16) bf g_S3l[(size_t)B * 64 * 4096];

__constant__ int cWM[13] = {0, 36864, 73728, 110592, 147456, 184320, 221184, 258048,
                            331776, 368640, 442368, 479232, 552960};
__constant__ int cK2[13] = {1152, 38016, 74880, 111744, 148608, 185472, 222336, 259200,
                            332928, 369792, 443520, 480384, 554112};
__constant__ int cCIN2[13] = {64, 64, 64, 64, 64, 64, 64, 128, 64, 128, 64, 128, 64};

// ---------------- helpers ----------------
__device__ __forceinline__ void fma2(unsigned long long& a, unsigned long long x, unsigned long long w)
{ asm("fma.rn.f32x2 %0, %1, %2, %0;" : "+l"(a) : "l"(x), "l"(w)); }
__device__ __forceinline__ unsigned long long pack2b(float a)
{ unsigned long long r; asm("mov.b64 %0, {%1, %1};" : "=l"(r) : "f"(a)); return r; }
__device__ __forceinline__ float2 unpack2(unsigned long long v)
{ float2 r; asm("mov.b64 {%0, %1}, %2;" : "=f"(r.x), "=f"(r.y) : "l"(v)); return r; }
__device__ __forceinline__ void cp16(uint32_t d, const void* s)
{ asm volatile("cp.async.cg.shared.global [%0], [%1], 16;" :: "r"(d), "l"(s) : "memory"); }
__device__ __forceinline__ void cp16z(uint32_t d, const void* s, int sz)
{ asm volatile("cp.async.cg.shared.global [%0], [%1], 16, %2;" :: "r"(d), "l"(s), "r"(sz) : "memory"); }
__device__ __forceinline__ void cp_commit()
{ asm volatile("cp.async.commit_group;" ::: "memory"); }
__device__ __forceinline__ void cp_wait1()
{ asm volatile("cp.async.wait_group 1;" ::: "memory"); }
__device__ __forceinline__ void cp_wait0()
{ asm volatile("cp.async.wait_group 0;" ::: "memory"); }
__device__ __forceinline__ float joinv(bf h, bf l)
{ return __bfloat162float(h) + __bfloat162float(l); }
__device__ __forceinline__ uint32_t splitp(float v0, float v1, uint32_t& lo)
{
    bf h0 = __float2bfloat16(v0), h1 = __float2bfloat16(v1);
    bf l0 = __float2bfloat16(v0 - __bfloat162float(h0));
    bf l1 = __float2bfloat16(v1 - __bfloat162float(h1));
    lo = (uint32_t)__bfloat16_as_ushort(l0) | ((uint32_t)__bfloat16_as_ushort(l1) << 16);
    return (uint32_t)__bfloat16_as_ushort(h0) | ((uint32_t)__bfloat16_as_ushort(h1) << 16);
}
__device__ __forceinline__ uint32_t lds32(uint32_t a)
{ uint32_t v; asm volatile("ld.shared.b32 %0, [%1];" : "=r"(v) : "r"(a)); return v; }
__device__ __forceinline__ void lds64(uint32_t* v, uint32_t a)
{ asm volatile("ld.shared.v2.b32 {%0, %1}, [%2];" : "=r"(v[0]), "=r"(v[1]) : "r"(a)); }
// D += A*B  (m16n8k16, bf16 in, fp32 accum)
__device__ __forceinline__ void mma16816(float* d, const uint32_t* a, const uint32_t* bq)
{
    asm volatile("mma.sync.aligned.m16n8k16.row.col.f32.bf16.bf16.f32 "
        "{%0,%1,%2,%3}, {%4,%5,%6,%7}, {%8,%9}, {%0,%1,%2,%3};"
        : "+f"(d[0]), "+f"(d[1]), "+f"(d[2]), "+f"(d[3])
        : "r"(a[0]), "r"(a[1]), "r"(a[2]), "r"(a[3]), "r"(bq[0]), "r"(bq[1]));
}

// ---------------- hypernet ----------------
__global__ void hyper1_kernel(const float* __restrict__ hp, const float* __restrict__ W1,
                              const float* __restrict__ b1, const float* __restrict__ W2,
                              const float* __restrict__ b2, float* __restrict__ l1)
{
    __shared__ float h1[B][32];
    int b = threadIdx.x >> 5, i = threadIdx.x & 31;
    if (threadIdx.x < B) l1[threadIdx.x] = 0.f;
    h1[b][i] = hp[b] * W1[i] + b1[i];
    __syncthreads();
    float a = b2[i];
#pragma unroll
    for (int k = 0; k < 32; k++) a += h1[b][k] * W2[i * 32 + k];
    g_h2[b * 32 + i] = a;
}

__global__ void weightgen_kernel(const float* __restrict__ Wo, const float* __restrict__ bo,
                                 float* __restrict__ l1out)
{
    __shared__ float sh2[B * 32];
    __shared__ float wsum[8][B];
    int tid = threadIdx.x;
    sh2[tid] = g_h2[tid];
    __syncthreads();
    int j = blockIdx.x * 256 + tid;
    float s[B];
#pragma unroll
    for (int b = 0; b < B; b++) s[b] = 0.f;
    if (j < OUTD) {
        float wr[32];
        const float* row = Wo + (size_t)j * 32;
#pragma unroll
        for (int i = 0; i < 32; i++) wr[i] = row[i];
        float bj = bo[j];
#pragma unroll
        for (int b = 0; b < B; b++) {
            float a = bj;
#pragma unroll
            for (int i = 0; i < 32; i++) a += wr[i] * sh2[b * 32 + i];
            float w = tanhf(a);
            g_w[(size_t)b * OUTD + j] = w;
            s[b] = fabsf(w);
        }
    }
    int warp = tid >> 5, lane = tid & 31;
#pragma unroll
    for (int b = 0; b < B; b++) {
        float v = s[b];
        for (int o = 16; o > 0; o >>= 1) v += __shfl_xor_sync(0xFFFFFFFFu, v, o);
        if (lane == 0) wsum[warp][b] = v;
    }
    __syncthreads();
    if (tid < B) {
        float a = 0.f;
#pragma unroll
        for (int w = 0; w < 8; w++) a += wsum[w][tid];
        atomicAdd(&l1out[tid], a);
    }
}

// ---------------- repack layer0 (fp32 pairs) ----------------
__global__ void repack0_kernel()
{
    int e = blockIdx.x * 256 + threadIdx.x;
    if (e >= B * 576) return;
    int b = e / 576, q = e - b * 576;
    int c = q / 288, t = q - c * 288, ocp = t / 9, k = t - ocp * 9;
    const float* wb = g_w + (size_t)b * OUTD;
    g_wp0[(size_t)b * 640 + (c * 32 + ocp) * 10 + k] =
        make_float2(wb[((2 * ocp) * 2 + c) * 9 + k], wb[((2 * ocp + 1) * 2 + c) * 9 + k]);
}

// ---------------- repack layers 1..13 into mma-B-fragment order, bf16 hi/lo -----
// per chunk g (4096 elems): idx = ((s*8 + t)*32 + lane)*4 + j*2 + h
//   oc = t*8 + lane/4 ; ch = cb*64 + s*16 + (lane%4)*2 + j*8 + h ; tap = kk
__global__ void repack_mm_kernel()
{
    int e = blockIdx.x * 256 + threadIdx.x;
    if (e >= B * WMTOT) return;
    int b = e / WMTOT, r = e - b * WMTOT;
    int l = 0;
#pragma unroll
    for (int i = 1; i < 13; i++)
        if (r >= cWM[i]) l = i;
    int rp = r - cWM[l];
    int cin = cCIN2[l], cblk = cin >> 6;
    int g = rp >> 12, idx = rp & 4095;
    int kk = g / cblk, cb = g - kk * cblk;
    int h = idx & 1, j = (idx >> 1) & 1, lane = (idx >> 2) & 31;
    int t = (idx >> 7) & 7, s = idx >> 10;
    int oc = t * 8 + (lane >> 2);
    int c = cb * 64 + s * 16 + (lane & 3) * 2 + j * 8 + h;
    float w = g_w[(size_t)b * OUTD + cK2[l] + ((oc * cin + c) * 9 + kk)];
    bf hh = __float2bfloat16(w);
    g_wmh[(size_t)b * WMTOT + r] = hh;
    g_wml[(size_t)b * WMTOT + r] = __float2bfloat16(w - __bfloat162float(hh));
}

// ---------------- layer 0: CIN=2 fp32 conv, NHWC bf16 hi/lo out ----------------
__global__ __launch_bounds__(256) void conv0_kernel(
    const float* __restrict__ zf, bf* __restrict__ oh, bf* __restrict__ ol,
    const float* __restrict__ wbuf)
{
    __shared__ float sIn[2 * 1156];
    __shared__ float2 sW[2 * 72];
    int b = blockIdx.z, ocg = blockIdx.y;
    int ty0 = (blockIdx.x >> 3) << 5, tx0 = (blockIdx.x & 7) << 5;
    int tid = threadIdx.x, tx = tid & 15, ty = tid >> 4;
    const float* inb = zf + (size_t)b * 131072;
    const float2* wpb = g_wp0 + (size_t)b * 640;

    for (int idx = tid; idx < 2 * 1156; idx += 256) {
        int cs = idx / 1156, rem = idx - cs * 1156;
        int r = rem / 34, cc = rem - r * 34;
        int gy = ty0 - 1 + r, gx = tx0 - 1 + cc;
        float v = 0.f;
        if ((unsigned)gy < 256u && (unsigned)gx < 256u)
            v = inb[(((size_t)gy << 8) + gx) * 2 + cs];
        sIn[idx] = v;
    }
    for (int idx = tid; idx < 144; idx += 256) {
        int cs = idx / 72, rem = idx - cs * 72, ocp = rem / 9, k = rem - ocp * 9;
        sW[idx] = wpb[(cs * 32 + ocg * 8 + ocp) * 10 + k];
    }
    __syncthreads();

    unsigned long long acc[8][4];
#pragma unroll
    for (int i = 0; i < 8; i++)
#pragma unroll
        for (int p = 0; p < 4; p++) acc[i][p] = 0ull;
#pragma unroll
    for (int cs = 0; cs < 2; cs++) {
        float xi[16];
#pragma unroll
        for (int r = 0; r < 4; r++)
#pragma unroll
            for (int cc = 0; cc < 4; cc++)
                xi[r * 4 + cc] = sIn[cs * 1156 + (2 * ty + r) * 34 + 2 * tx + cc];
#pragma unroll
        for (int ky = 0; ky < 3; ky++)
#pragma unroll
            for (int kx = 0; kx < 3; kx++) {
                unsigned long long xx[4];
#pragma unroll
                for (int py = 0; py < 2; py++)
#pragma unroll
                    for (int px = 0; px < 2; px++)
                        xx[py * 2 + px] = pack2b(xi[(py + ky) * 4 + (px + kx)]);
#pragma unroll
                for (int o = 0; o < 8; o++) {
                    unsigned long long w =
                        *reinterpret_cast<const unsigned long long*>(&sW[cs * 72 + o * 9 + ky * 3 + kx]);
#pragma unroll
                    for (int p = 0; p < 4; p++) fma2(acc[o][p], xx[p], w);
                }
            }
    }
    const float* wb = wbuf + (size_t)b * OUTD;
#pragma unroll
    for (int o = 0; o < 8; o++) {
        int oc = (ocg * 8 + o) * 2;
        float b0 = wb[591104 + oc], b1 = wb[591104 + oc + 1];
#pragma unroll
        for (int py = 0; py < 2; py++)
#pragma unroll
            for (int px = 0; px < 2; px++) {
                float2 v = unpack2(acc[o][py * 2 + px]);
                float v0 = fmaxf(v.x + b0, 0.f), v1 = fmaxf(v.y + b1, 0.f);
                uint32_t lo, hi = splitp(v0, v1, lo);
                int p = (ty0 + 2 * ty + py) * 256 + tx0 + 2 * tx + px;
                size_t off = ((size_t)b * 65536 + p) * 64 + oc;
                *(uint32_t*)(oh + off) = hi;
                *(uint32_t*)(ol + off) = lo;
            }
    }
}

// ---------------- mma.sync conv layer (CIN = 64 or 128) ----------------
// Block: 128 px x 64 oc. 8 warps: warp w -> px tile 32*(w&3), oc tile 32*(w>>2).
// Per buffer (48KB): AH 16K | AL 16K | BH 8K (frag-ordered) | BL 8K.
#define CMM_SMEM 98304
template<int CIN>
__global__ __launch_bounds__(256, 2) void convmm_kernel(
    const bf* __restrict__ inh, const bf* __restrict__ inl,
    bf* __restrict__ outh, bf* __restrict__ outl,
    const float* __restrict__ wbuf, int wmoff, int boff, int H, int lgH)
{
    constexpr int CBLK = CIN / 64;
    constexpr int G = 9 * CBLK;
    extern __shared__ __align__(128) char smem[];
    __shared__ float sbias[64];
    const int tid = threadIdx.x;
    const int b = blockIdx.z;
    const int p0 = blockIdx.x * 128;
    const int HH = H * H;
    uint32_t sb0 = (uint32_t)__cvta_generic_to_shared(smem);

    if (tid < 64) sbias[tid] = wbuf[(size_t)b * OUTD + boff + tid];

    const bf* ibh = inh + (size_t)b * HH * CIN;
    const bf* ibl = inl + (size_t)b * HH * CIN;
    const bf* wch = g_wmh + (size_t)b * WMTOT + wmoff;
    const bf* wcl = g_wml + (size_t)b * WMTOT + wmoff;

    const int ar = tid >> 1, aj0 = (tid & 1) * 4;        // A staging: row, chunk range
    const int py = p0 + ar;
    const int ay = py >> lgH, ax = py & (H - 1);

    auto stage = [&](int g, int buf) {
        const uint32_t AH = sb0 + buf * 49152, AL = AH + 16384;
        const uint32_t BH = AH + 32768, BL = AH + 40960;
        const int kk = g / CBLK, cb = g - kk * CBLK;
        const int dy = kk / 3 - 1, dx = kk - (kk / 3) * 3 - 1;
        int gy = ay + dy, gx = ax + dx;
        bool ok = ((unsigned)gy < (unsigned)H) && ((unsigned)gx < (unsigned)H);
        size_t q = ok ? ((size_t)(gy * H + gx) * CIN + cb * 64) : 0;
        const char* sh = (const char*)(ibh + q);
        const char* sl = (const char*)(ibl + q);
        int sz = ok ? 16 : 0;
        uint32_t ro = (uint32_t)ar * 128u, sw = (uint32_t)((ar & 7) << 4);
#pragma unroll
        for (int j = aj0; j < aj0 + 4; j++) {
            uint32_t o = ro + (((uint32_t)j * 16u) ^ sw);
            cp16z(AH + o, sh + j * 16, sz);
            cp16z(AL + o, sl + j * 16, sz);
        }
        // B: 512 16B chunks per precision, linear (already fragment-ordered)
        const char* wh = (const char*)(wch + (size_t)g * 4096);
        const char* wl = (const char*)(wcl + (size_t)g * 4096);
#pragma unroll
        for (int j = 0; j < 2; j++) {
            uint32_t o = (uint32_t)(tid * 2 + j) * 16u;
            cp16(BH + o, wh + o);
            cp16(BL + o, wl + o);
        }
    };

    const int lane = tid & 31, w = tid >> 5;
    const int mrow = (w & 3) * 32;      // pixel tile base
    const int nt0 = (w >> 2) * 4;       // first n8-tile index (oc base = nt0*8)

    float acc[2][4][4];
#pragma unroll
    for (int m = 0; m < 2; m++)
#pragma unroll
        for (int n = 0; n < 4; n++)
#pragma unroll
            for (int i = 0; i < 4; i++) acc[m][n][i] = 0.f;

    stage(0, 0);
    cp_commit();

    for (int g = 0; g < G; g++) {
        if (g + 1 < G) { stage(g + 1, (g + 1) & 1); cp_commit(); cp_wait1(); }
        else           { cp_wait0(); }
        __syncthreads();

        const uint32_t AH = sb0 + (g & 1) * 49152, AL = AH + 16384;
        const uint32_t BH = AH + 32768, BL = AH + 40960;

#pragma unroll
        for (int s = 0; s < 4; s++) {
            uint32_t a_h[2][4], a_l[2][4];
#pragma unroll
            for (int m = 0; m < 2; m++) {
                uint32_t rA = (uint32_t)(mrow + m * 16 + (lane >> 2));
                uint32_t rB = rA + 8;
                uint32_t cA = (uint32_t)((lane & 3) * 4);
                uint32_t oA0 = rA * 128 + (((uint32_t)(s * 32)) ^ ((rA & 7) << 4)) + cA;
                uint32_t oA1 = rA * 128 + (((uint32_t)(s * 32 + 16)) ^ ((rA & 7) << 4)) + cA;
                uint32_t oB0 = rB * 128 + (((uint32_t)(s * 32)) ^ ((rB & 7) << 4)) + cA;
                uint32_t oB1 = rB * 128 + (((uint32_t)(s * 32 + 16)) ^ ((rB & 7) << 4)) + cA;
                a_h[m][0] = lds32(AH + oA0); a_h[m][1] = lds32(AH + oB0);
                a_h[m][2] = lds32(AH + oA1); a_h[m][3] = lds32(AH + oB1);
                a_l[m][0] = lds32(AL + oA0); a_l[m][1] = lds32(AL + oB0);
                a_l[m][2] = lds32(AL + oA1); a_l[m][3] = lds32(AL + oB1);
            }
            uint32_t b_h[4][2], b_l[4][2];
#pragma unroll
            for (int n = 0; n < 4; n++) {
                uint32_t o = (uint32_t)(((s * 8 + nt0 + n) * 32 + lane) * 8);
                lds64(b_h[n], BH + o);
                lds64(b_l[n], BL + o);
            }
#pragma unroll
            for (int m = 0; m < 2; m++)
#pragma unroll
                for (int n = 0; n < 4; n++) {
                    mma16816(acc[m][n], a_h[m], b_h[n]);
                    mma16816(acc[m][n], a_h[m], b_l[n]);
                    mma16816(acc[m][n], a_l[m], b_h[n]);
                }
        }
        __syncthreads();
    }

    // epilogue: bias + relu + hi/lo split + NHWC store
#pragma unroll
    for (int m = 0; m < 2; m++) {
        int pr0 = p0 + mrow + m * 16 + (lane >> 2);
#pragma unroll
        for (int n = 0; n < 4; n++) {
            int oc = (nt0 + n) * 8 + (lane & 3) * 2;
            float bs0 = sbias[oc], bs1 = sbias[oc + 1];
#pragma unroll
            for (int half = 0; half < 2; half++) {
                int pr = pr0 + half * 8;
                float v0 = fmaxf(acc[m][n][half * 2 + 0] + bs0, 0.f);
                float v1 = fmaxf(acc[m][n][half * 2 + 1] + bs1, 0.f);
                uint32_t lo, hi = splitp(v0, v1, lo);
                size_t off = ((size_t)b * HH + pr) * 64 + oc;
                *(uint32_t*)(outh + off) = hi;
                *(uint32_t*)(outl + off) = lo;
            }
        }
    }
}

// ---------------- 2x2 maxpool (NHWC hi/lo) ----------------
__global__ void maxpool_bf(const bf* __restrict__ ih, const bf* __restrict__ il,
                           bf* __restrict__ oh, bf* __restrict__ ol, int H)
{
    int Wo = H >> 1;
    int total = B * Wo * Wo * 64;
    int idx = blockIdx.x * 256 + threadIdx.x;
    if (idx >= total) return;
    int c = idx & 63, t = idx >> 6;
    int xo = t % Wo; t /= Wo;
    int yo = t % Wo; int b = t / Wo;
    size_t base = (((size_t)b * H + 2 * yo) * H + 2 * xo) * 64 + c;
    size_t rs = (size_t)H * 64;
    float v = fmaxf(fmaxf(joinv(ih[base], il[base]), joinv(ih[base + 64], il[base + 64])),
                    fmaxf(joinv(ih[base + rs], il[base + rs]), joinv(ih[base + rs + 64], il[base + rs + 64])));
    bf h = __float2bfloat16(v);
    oh[idx] = h;
    ol[idx] = __float2bfloat16(v - __bfloat162float(h));
}

// ---------------- bilinear x2 upsample + concat (NHWC hi/lo, 128ch out) ----------------
__global__ void upconcat_bf(const bf* __restrict__ ih, const bf* __restrict__ il,
                            const bf* __restrict__ skh, const bf* __restrict__ skl,
                            bf* __restrict__ oh, bf* __restrict__ ol, int H)
{
    int Ho = H * 2;
    int total = B * Ho * Ho * 128;
    int idx = blockIdx.x * 256 + threadIdx.x;
    if (idx >= total) return;
    int c = idx & 127, t = idx >> 7;
    int xo = t % Ho; t /= Ho;
    int yo = t % Ho; int b = t / Ho;
    if (c >= 64) {
        size_t s = (((size_t)b * Ho + yo) * Ho + xo) * 64 + (c - 64);
        oh[idx] = skh[s];
        ol[idx] = skl[s];
        return;
    }
    float ys = (float)yo * (float)(H - 1) / (float)(Ho - 1);
    float xs = (float)xo * (float)(H - 1) / (float)(Ho - 1);
    int y0 = (int)floorf(ys); int y1 = min(y0 + 1, H - 1);
    int x0 = (int)floorf(xs); int x1 = min(x0 + 1, H - 1);
    float wy = ys - (float)y0, wx = xs - (float)x0;
    const bf* ph = ih + (size_t)b * H * H * 64 + c;
    const bf* pl = il + (size_t)b * H * H * 64 + c;
#define AT(y, x) joinv(ph[((size_t)(y) * H + (x)) * 64], pl[((size_t)(y) * H + (x)) * 64])
    float r0 = AT(y0, x0) * (1.f - wy) + AT(y1, x0) * wy;
    float r1 = AT(y0, x1) * (1.f - wy) + AT(y1, x1) * wy;
#undef AT
    float v = r0 * (1.f - wx) + r1 * wx;
    bf h = __float2bfloat16(v);
    oh[idx] = h;
    ol[idx] = __float2bfloat16(v - __bfloat162float(h));
}

// ---------------- final 1x1 conv (64->2) + residual, NHWC ----------------
__global__ void final_bf(const bf* __restrict__ ih, const bf* __restrict__ il,
                         const float* __restrict__ zf, const float* __restrict__ wbuf,
                         float* __restrict__ out)
{
    __shared__ float sw[130];
    int b = blockIdx.y, tid = threadIdx.x;
    const float* wb = wbuf + (size_t)b * OUTD;
    if (tid < 128) sw[tid] = wb[590976 + tid];
    else if (tid < 130) sw[tid] = wb[592000 + (tid - 128)];
    __syncthreads();
    int hw = blockIdx.x * 256 + tid;
    const bf* ph = ih + ((size_t)b * 65536 + hw) * 64;
    const bf* pl = il + ((size_t)b * 65536 + hw) * 64;
    float a0 = sw[128], a1 = sw[129];
#pragma unroll 16
    for (int c = 0; c < 64; c++) {
        float v = joinv(ph[c], pl[c]);
        a0 = fmaf(v, sw[c], a0);
        a1 = fmaf(v, sw[64 + c], a1);
    }
    size_t o = ((size_t)b * 65536 + hw) * 2;
    out[o] = zf[o] + a0;
    out[o + 1] = zf[o + 1] + a1;
}

// ---------------- host ----------------
static const int WMh[13] = {0, 36864, 73728, 110592, 147456, 184320, 221184, 258048,
                            331776, 368640, 442368, 479232, 552960};
static const int CINh[13] = {64, 64, 64, 64, 64, 64, 64, 128, 64, 128, 64, 128, 64};

static inline void launch_mm(const bf* ih, const bf* il, bf* oh, bf* ol,
                             const float* pw, int layer, int H, int lgH)
{
    dim3 gs((H * H) / 128, 1, B);
    int wmoff = WMh[layer - 1];
    int boff = 591104 + 64 * layer;
    if (CINh[layer - 1] == 64)
        convmm_kernel<64><<<gs, 256, CMM_SMEM>>>(ih, il, oh, ol, pw, wmoff, boff, H, lgH);
    else
        convmm_kernel<128><<<gs, 256, CMM_SMEM>>>(ih, il, oh, ol, pw, wmoff, boff, H, lgH);
}

extern "C" void kernel_launch(void* const* d_in, const int* in_sizes, int n_in,
                              void* d_out, int out_size)
{
    const float* zf = (const float*)d_in[0];
    const float* hp = (const float*)d_in[2];
    const float* W1 = (const float*)d_in[3];
    const float* b1 = (const float*)d_in[4];
    const float* W2 = (const float*)d_in[5];
    const float* b2 = (const float*)d_in[6];
    const float* Wo = (const float*)d_in[7];
    const float* bo = (const float*)d_in[8];
    float* out = (float*)d_out;
    float* l1 = out + (size_t)B * 131072;

    cudaFuncSetAttribute(convmm_kernel<64>, cudaFuncAttributeMaxDynamicSharedMemorySize, CMM_SMEM);
    cudaFuncSetAttribute(convmm_kernel<128>, cudaFuncAttributeMaxDynamicSharedMemorySize, CMM_SMEM);

    float* pW;
    bf *Ah, *Al, *Bh, *Bl, *S1h, *S1l, *S2h, *S2l, *S3h, *S3l;
    cudaGetSymbolAddress((void**)&pW, g_w);
    cudaGetSymbolAddress((void**)&Ah, g_Ah);
    cudaGetSymbolAddress((void**)&Al, g_Al);
    cudaGetSymbolAddress((void**)&Bh, g_Bh);
    cudaGetSymbolAddress((void**)&Bl, g_Bl);
    cudaGetSymbolAddress((void**)&S1h, g_S1h);
    cudaGetSymbolAddress((void**)&S1l, g_S1l);
    cudaGetSymbolAddress((void**)&S2h, g_S2h);
    cudaGetSymbolAddress((void**)&S2l, g_S2l);
    cudaGetSymbolAddress((void**)&S3h, g_S3h);
    cudaGetSymbolAddress((void**)&S3l, g_S3l);

    hyper1_kernel<<<1, 256>>>(hp, W1, b1, W2, b2, l1);
    weightgen_kernel<<<(OUTD + 255) / 256, 256>>>(Wo, bo, l1);
    repack0_kernel<<<(B * 576 + 255) / 256, 256>>>();
    repack_mm_kernel<<<(B * WMTOT + 255) / 256, 256>>>();

    // encoder
    conv0_kernel<<<dim3(64, 4, B), 256>>>(zf, Ah, Al, pW);
    launch_mm(Ah, Al, S1h, S1l, pW, 1, 256, 8);
    { int n = B * 128 * 128 * 64; maxpool_bf<<<(n + 255) / 256, 256>>>(S1h, S1l, Bh, Bl, 256); }
    launch_mm(Bh, Bl, Ah, Al, pW, 2, 128, 7);
    launch_mm(Ah, Al, S2h, S2l, pW, 3, 128, 7);
    { int n = B * 64 * 64 * 64; maxpool_bf<<<(n + 255) / 256, 256>>>(S2h, S2l, Bh, Bl, 128); }
    launch_mm(Bh, Bl, Ah, Al, pW, 4, 64, 6);
    launch_mm(Ah, Al, S3h, S3l, pW, 5, 64, 6);
    { int n = B * 32 * 32 * 64; maxpool_bf<<<(n + 255) / 256, 256>>>(S3h, S3l, Bh, Bl, 64); }
    launch_mm(Bh, Bl, Ah, Al, pW, 6, 32, 5);
    launch_mm(Ah, Al, Bh, Bl, pW, 7, 32, 5);

    // decoder
    { int n = B * 64 * 64 * 128; upconcat_bf<<<(n + 255) / 256, 256>>>(Bh, Bl, S3h, S3l, Ah, Al, 32); }
    launch_mm(Ah, Al, Bh, Bl, pW, 8, 64, 6);
    launch_mm(Bh, Bl, Ah, Al, pW, 9, 64, 6);
    { int n = B * 128 * 128 * 128; upconcat_bf<<<(n + 255) / 256, 256>>>(Ah, Al, S2h, S2l, Bh, Bl, 64); }
    launch_mm(Bh, Bl, Ah, Al, pW, 10, 128, 7);
    launch_mm(Ah, Al, Bh, Bl, pW, 11, 128, 7);
    { int n = B * 256 * 256 * 128; upconcat_bf<<<(n + 255) / 256, 256>>>(Bh, Bl, S1h, S1l, Ah, Al, 128); }
    launch_mm(Ah, Al, Bh, Bl, pW, 12, 256, 8);
    launch_mm(Bh, Bl, Ah, Al, pW, 13, 256, 8);

    final_bf<<<dim3(256, B), 256>>>(Ah, Al, zf, pW, out);
}